// round 3
// baseline (speedup 1.0000x reference)
#include <cuda_runtime.h>
#include <math.h>

// Problem constants
constexpr int TYc = 128;   // decode steps
constexpr int Bc  = 64;    // batch
constexpr int TXc = 400;   // encoder length
constexpr int Hc  = 512;
constexpr int Cc  = 512;
constexpr int NHc = 8;
constexpr int G4c = 4 * Hc;  // 2048
constexpr int NBc = 128;     // persistent blocks (<=148 SMs -> all resident)
constexpr int NTc = 256;     // threads per block

// ---------------- device scratch (static: no allocations allowed) ----------
__device__ float g_pctx[(size_t)TXc * Bc * Cc];   // [t][b][c] key projection
__device__ float g_pv  [(size_t)TXc * Bc * Cc];   // [t][b][c] value projection
__device__ float g_xw  [(size_t)TYc * Bc * G4c];  // [t][b][4H] x@W_ih.T + b_ih + b_hh
__device__ float g_bias4[G4c];
__device__ float g_h[2][Bc * Hc];
__device__ float g_c[2][Bc * Hc];
__device__ float g_hq [Bc * Cc];
__device__ float g_e  [Bc * NHc * TXc];   // scores [b][h][t]
__device__ float g_w  [Bc * NHc * TXc];   // softmax weights [b][h][t]
__device__ float g_acc[Bc * TXc];         // coverage accumulator
__device__ float g_ctx[Bc * Cc];          // attention context vector
__device__ float g_att[Bc * Cc];          // ctx @ W_concat.T (pre-LN)
__device__ unsigned g_bar_count;          // zero-initialized
__device__ unsigned g_bar_gen;

__device__ __forceinline__ float sigf(float x) { return 1.0f / (1.0f + __expf(-x)); }
__device__ __forceinline__ float tanh_acc(float x) {
    // tanh(x) = 1 - 2/(exp(2|x|)+1), abs err ~1e-7; exp overflow -> 1 (correct)
    float e = __expf(2.0f * fabsf(x));
    float r = 1.0f - 2.0f / (e + 1.0f);
    return copysignf(r, x);
}

// ---------------- grid-wide barrier (all NBc blocks resident) ---------------
__device__ __forceinline__ void gsync() {
    __threadfence();                 // order my writes; CCTL.IVALL on sm_103a
    __syncthreads();
    if (threadIdx.x == 0) {
        unsigned gen = *(volatile unsigned*)&g_bar_gen;
        if (atomicAdd(&g_bar_count, 1u) == NBc - 1) {
            g_bar_count = 0;
            __threadfence();
            atomicExch(&g_bar_gen, gen + 1);
        } else {
            while (*(volatile unsigned*)&g_bar_gen == gen) {}
        }
        __threadfence();             // invalidate L1 before reading others' data
    }
    __syncthreads();
}

// ---------------- precompute: C[m][n] = sum_k A[m][k]*B[n][k] + bias[n] -----
// K fixed at 512. tag selects output buffer (0=pctx,1=pv,2=xw with g_bias4).
__global__ void sgemm_nt_bias(const float* __restrict__ A, const float* __restrict__ Bm,
                              const float* __restrict__ bias, int N, int tag) {
    float* Cout = (tag == 0) ? g_pctx : (tag == 1) ? g_pv : g_xw;
    const float* bp = (tag == 2) ? g_bias4 : bias;
    const int K = 512;
    __shared__ float As[8][128];
    __shared__ float Bs[8][128];
    int bm = blockIdx.y * 128, bn = blockIdx.x * 128;
    int tid = threadIdx.x;
    int lr = tid >> 1, lc = (tid & 1) * 4;
    int ty = tid >> 4, tx = tid & 15;
    float acc[8][8] = {};
    const float* Ap = A + (size_t)(bm + lr) * K + lc;
    const float* Bp = Bm + (size_t)(bn + lr) * K + lc;
    for (int k0 = 0; k0 < K; k0 += 8) {
        float4 a4 = *(const float4*)(Ap + k0);
        float4 b4 = *(const float4*)(Bp + k0);
        As[lc][lr] = a4.x; As[lc + 1][lr] = a4.y; As[lc + 2][lr] = a4.z; As[lc + 3][lr] = a4.w;
        Bs[lc][lr] = b4.x; Bs[lc + 1][lr] = b4.y; Bs[lc + 2][lr] = b4.z; Bs[lc + 3][lr] = b4.w;
        __syncthreads();
#pragma unroll
        for (int kk = 0; kk < 8; kk++) {
            float ar[8], br[8];
            *(float4*)&ar[0] = *(const float4*)&As[kk][ty * 8];
            *(float4*)&ar[4] = *(const float4*)&As[kk][ty * 8 + 4];
            *(float4*)&br[0] = *(const float4*)&Bs[kk][tx * 8];
            *(float4*)&br[4] = *(const float4*)&Bs[kk][tx * 8 + 4];
#pragma unroll
            for (int i = 0; i < 8; i++)
#pragma unroll
                for (int j = 0; j < 8; j++) acc[i][j] = fmaf(ar[i], br[j], acc[i][j]);
        }
        __syncthreads();
    }
#pragma unroll
    for (int i = 0; i < 8; i++) {
        size_t m = bm + ty * 8 + i;
#pragma unroll
        for (int j = 0; j < 8; j += 4) {
            int n = bn + tx * 8 + j;
            float4 o;
            o.x = acc[i][j + 0] + bp[n + 0];
            o.y = acc[i][j + 1] + bp[n + 1];
            o.z = acc[i][j + 2] + bp[n + 2];
            o.w = acc[i][j + 3] + bp[n + 3];
            *(float4*)&Cout[m * N + n] = o;
        }
    }
}

__global__ void combine_bias(const float* __restrict__ bi, const float* __restrict__ bh) {
    int i = blockIdx.x * 256 + threadIdx.x;
    if (i < G4c) g_bias4[i] = bi[i] + bh[i];
}

__global__ void init_state(const float* __restrict__ h0, const float* __restrict__ c0,
                           const float* __restrict__ cov) {
    int i = blockIdx.x * 256 + threadIdx.x;
    if (i < Bc * Hc) { g_h[0][i] = h0[i]; g_c[0][i] = c0[i]; }
    if (i < Bc * TXc) g_acc[i] = cov[i];
}

// ---------------- the whole recurrent loop as ONE persistent kernel ---------
__global__ void __launch_bounds__(NTc, 1)
decoder_persistent(const float* __restrict__ xmask, const float* __restrict__ ymask,
                   const float* __restrict__ W_hh, const float* __restrict__ W_comb,
                   const float* __restrict__ U_att, const float* __restrict__ W_cov,
                   const float* __restrict__ W_concat, const float* __restrict__ ln_g,
                   const float* __restrict__ ln_b,
                   float* __restrict__ o_hs, float* __restrict__ o_cs,
                   float* __restrict__ o_ss, float* __restrict__ o_atts,
                   float* __restrict__ o_dists, float* __restrict__ o_Cs) {
    __shared__ float sm[8256];   // phase-overlaid scratch (max 33 KB)
    const int tid  = threadIdx.x;
    const int bk   = blockIdx.x;
    const int wid  = tid >> 5;
    const int lane = tid & 31;
    const int tx   = tid & 63;   // batch lane for GEMM phases
    const int ty   = tid >> 6;   // 0..3

    for (int t = 0; t < TYc; t++) {
        const int ph = t & 1;    // read g_h[ph]/g_c[ph], write [ph^1]

        // ===== Phase A: gates = h_prev @ W_hh.T (+xw), LSTM cell update =====
        {
            const int u0 = bk * 4;
            const float* hprev = g_h[ph];
            float* Wt = sm;            // [16][256]
            float* Ht = sm + 4096;     // [64][65]
            float a0 = 0.f, a1 = 0.f, a2 = 0.f, a3 = 0.f;
            for (int kh = 0; kh < 2; kh++) {
#pragma unroll
                for (int q = 0; q < 4; q++) {           // load W tile 16x256
                    int idx = q * 256 + tid;            // float4 index
                    int r = idx >> 6;
                    int k4 = (idx & 63) * 4;
                    int j = (r >> 2) * Hc + u0 + (r & 3);
                    float4 v = *(const float4*)&W_hh[(size_t)j * Hc + kh * 256 + k4];
                    float* w = &Wt[r * 256 + k4];
                    w[0] = v.x; w[1] = v.y; w[2] = v.z; w[3] = v.w;
                }
                for (int kt = 0; kt < 4; kt++) {
                    __syncthreads();
#pragma unroll
                    for (int q = 0; q < 4; q++) {       // load h tile 64x64
                        int idx = q * 256 + tid;
                        int b = idx >> 4;
                        int k4 = (idx & 15) * 4;
                        float4 v = *(const float4*)&hprev[b * Hc + kh * 256 + kt * 64 + k4];
                        float* hh = &Ht[b * 65 + k4];
                        hh[0] = v.x; hh[1] = v.y; hh[2] = v.z; hh[3] = v.w;
                    }
                    __syncthreads();
#pragma unroll
                    for (int kk = 0; kk < 64; kk++) {
                        float hv = Ht[tx * 65 + kk];
                        int kw = kt * 64 + kk;
                        a0 = fmaf(Wt[(0 * 4 + ty) * 256 + kw], hv, a0);
                        a1 = fmaf(Wt[(1 * 4 + ty) * 256 + kw], hv, a1);
                        a2 = fmaf(Wt[(2 * 4 + ty) * 256 + kw], hv, a2);
                        a3 = fmaf(Wt[(3 * 4 + ty) * 256 + kw], hv, a3);
                    }
                }
                __syncthreads();   // before W tile reload
            }
            // cell update: one (b=tx, u=u0+ty) per thread
            const int u = u0 + ty;
            const float* xw = &g_xw[((size_t)t * Bc + tx) * G4c];
            float gi = a0 + xw[u];
            float gf = a1 + xw[Hc + u];
            float gg = a2 + xw[2 * Hc + u];
            float go = a3 + xw[3 * Hc + u];
            float co = g_c[ph][tx * Hc + u];
            float ho = hprev[tx * Hc + u];
            float c1 = sigf(gf) * co + sigf(gi) * tanh_acc(gg);
            float h1 = sigf(go) * tanh_acc(c1);
            float m = ymask[t * Bc + tx];
            h1 = m * h1 + (1.0f - m) * ho;
            c1 = m * c1 + (1.0f - m) * co;
            g_h[ph ^ 1][tx * Hc + u] = h1;
            g_c[ph ^ 1][tx * Hc + u] = c1;
            size_t oo = ((size_t)t * Bc + tx) * Hc + u;
            o_hs[oo] = h1; o_ss[oo] = h1; o_cs[oo] = c1;
        }
        gsync();

        // ===== Phase B: hq = [h1,c1] @ W_comb.T (K=1024) =====
        {
            const int c0 = bk * 4;
            float* Wt = sm;            // [4][1024]
            float* St = sm + 4096;     // [64][65]
#pragma unroll
            for (int q = 0; q < 4; q++) {
                int idx = q * 256 + tid;
                int r = idx >> 8;
                int k4 = (idx & 255) * 4;
                float4 v = *(const float4*)&W_comb[(size_t)(c0 + r) * 1024 + k4];
                float* w = &Wt[r * 1024 + k4];
                w[0] = v.x; w[1] = v.y; w[2] = v.z; w[3] = v.w;
            }
            float acc = 0.f;
            for (int kt = 0; kt < 16; kt++) {
                const float* src = (kt < 8) ? g_h[ph ^ 1] : g_c[ph ^ 1];
                int koff = (kt & 7) * 64;
                __syncthreads();
#pragma unroll
                for (int q = 0; q < 4; q++) {
                    int idx = q * 256 + tid;
                    int b = idx >> 4;
                    int k4 = (idx & 15) * 4;
                    float4 v = *(const float4*)&src[b * Hc + koff + k4];
                    float* s = &St[b * 65 + k4];
                    s[0] = v.x; s[1] = v.y; s[2] = v.z; s[3] = v.w;
                }
                __syncthreads();
#pragma unroll
                for (int kk = 0; kk < 64; kk++)
                    acc = fmaf(Wt[ty * 1024 + kt * 64 + kk], St[tx * 65 + kk], acc);
            }
            g_hq[tx * Cc + c0 + ty] = acc;
        }
        gsync();

        // ===== Phase C: e[b][h][t'] = sum_d tanh(pctx+hq+cov)*xm*U =====
        {
            for (int i = tid; i < 1024; i += NTc)
                sm[i] = (i < 512) ? U_att[i] : W_cov[i - 512];
            __syncthreads();
            const int wg = bk * 8 + wid;     // 0..1023, 16 warps per b
            const int cb = wg >> 4;          // batch
            const int t0 = wg & 15;
            float hqr[16];
#pragma unroll
            for (int i = 0; i < 16; i++) hqr[i] = g_hq[cb * Cc + i * 32 + lane];
            for (int i = 0; i < 25; i++) {
                int ts = t0 + 16 * i;        // encoder position
                const float* pc = &g_pctx[((size_t)ts * Bc + cb) * Cc];
                float cov = g_acc[cb * TXc + ts];
                float xm = xmask[ts * Bc + cb];
#pragma unroll
                for (int hh = 0; hh < 8; hh++) {
                    float s = 0.f;
#pragma unroll
                    for (int ii = 0; ii < 2; ii++) {
                        int c = hh * 64 + ii * 32 + lane;
                        float arg = pc[c] + hqr[hh * 2 + ii] + cov * sm[512 + c];
                        s = fmaf(tanh_acc(arg) * xm, sm[c], s);
                    }
#pragma unroll
                    for (int o = 16; o > 0; o >>= 1) s += __shfl_xor_sync(0xffffffffu, s, o);
                    if (lane == 0) g_e[(cb * NHc + hh) * TXc + ts] = s;
                }
            }
        }
        gsync();

        // ===== Phase D: softmax over t' per (b,h); coverage/dists outputs ===
        {
            const int wg = bk * 8 + wid;
            if (wg < Bc * NHc) {
                const int b = wg >> 3, hh = wg & 7;
                const float* ep = &g_e[wg * TXc];
                float ev[13];
                float mx = -3.4e38f;
#pragma unroll
                for (int i = 0; i < 13; i++) {
                    int ts = lane + i * 32;
                    float v = (ts < TXc) ? ep[ts] : -3.4e38f;
                    ev[i] = v; mx = fmaxf(mx, v);
                }
#pragma unroll
                for (int o = 16; o > 0; o >>= 1) mx = fmaxf(mx, __shfl_xor_sync(0xffffffffu, mx, o));
                float sum = 0.f;
#pragma unroll
                for (int i = 0; i < 13; i++) {
                    int ts = lane + i * 32;
                    if (ts < TXc) {
                        float v = __expf(ev[i] - mx) * xmask[ts * Bc + b];
                        ev[i] = v; sum += v;
                    }
                }
#pragma unroll
                for (int o = 16; o > 0; o >>= 1) sum += __shfl_xor_sync(0xffffffffu, sum, o);
                float inv = 1.0f / (sum + 1e-6f);
                float* wp = &g_w[wg * TXc];
#pragma unroll
                for (int i = 0; i < 13; i++) {
                    int ts = lane + i * 32;
                    if (ts < TXc) {
                        float w = ev[i] * inv;
                        wp[ts] = w;
                        if (hh == 0) {
                            float a = g_acc[b * TXc + ts];
                            o_Cs[((size_t)t * Bc + b) * TXc + ts] = a;
                            o_dists[((size_t)t * Bc + b) * TXc + ts] = w;
                            g_acc[b * TXc + ts] = a + w;
                        }
                    }
                }
            }
        }
        gsync();

        // ===== Phase E: ctx[b][c] = sum_t' w[b][h(c)][t'] * pv[t'][b][c] ====
        {
            const int b = bk >> 1, half = bk & 1;
            for (int idx = tid; idx < 4 * TXc; idx += NTc) {
                int hh = idx / TXc, ts = idx - hh * TXc;
                sm[idx] = g_w[(b * NHc + half * 4 + hh) * TXc + ts];
            }
            __syncthreads();
            const int c = half * 256 + tid;
            const float* wsp = &sm[(tid >> 6) * TXc];
            const float* pvp = &g_pv[(size_t)b * Cc + c];
            float a0 = 0.f, a1 = 0.f, a2 = 0.f, a3 = 0.f;
#pragma unroll 2
            for (int ts = 0; ts < TXc; ts += 4) {
                a0 = fmaf(pvp[(size_t)(ts + 0) * Bc * Cc], wsp[ts + 0], a0);
                a1 = fmaf(pvp[(size_t)(ts + 1) * Bc * Cc], wsp[ts + 1], a1);
                a2 = fmaf(pvp[(size_t)(ts + 2) * Bc * Cc], wsp[ts + 2], a2);
                a3 = fmaf(pvp[(size_t)(ts + 3) * Bc * Cc], wsp[ts + 3], a3);
            }
            g_ctx[b * Cc + c] = (a0 + a1) + (a2 + a3);
        }
        gsync();

        // ===== Phase F1: att = ctx @ W_concat.T (K=512) =====
        {
            const int c0 = bk * 4;
            float* Wt = sm;            // [4][512]
            float* St = sm + 2048;     // [64][65]
#pragma unroll
            for (int q = 0; q < 2; q++) {
                int idx = q * 256 + tid;
                int r = idx >> 7;
                int k4 = (idx & 127) * 4;
                float4 v = *(const float4*)&W_concat[(size_t)(c0 + r) * Cc + k4];
                float* w = &Wt[r * 512 + k4];
                w[0] = v.x; w[1] = v.y; w[2] = v.z; w[3] = v.w;
            }
            float acc = 0.f;
            for (int kt = 0; kt < 8; kt++) {
                __syncthreads();
#pragma unroll
                for (int q = 0; q < 4; q++) {
                    int idx = q * 256 + tid;
                    int b = idx >> 4;
                    int k4 = (idx & 15) * 4;
                    float4 v = *(const float4*)&g_ctx[b * Cc + kt * 64 + k4];
                    float* s = &St[b * 65 + k4];
                    s[0] = v.x; s[1] = v.y; s[2] = v.z; s[3] = v.w;
                }
                __syncthreads();
#pragma unroll
                for (int kk = 0; kk < 64; kk++)
                    acc = fmaf(Wt[ty * 512 + kt * 64 + kk], St[tx * 65 + kk], acc);
            }
            g_att[tx * Cc + c0 + ty] = acc;
        }
        gsync();

        // ===== Phase F2: LayerNorm -> o_atts =====
        {
            if (bk < Bc) {
                const int b = bk;
                float v0 = g_att[b * Cc + tid];
                float v1 = g_att[b * Cc + 256 + tid];
                float s = v0 + v1;
#pragma unroll
                for (int o = 16; o > 0; o >>= 1) s += __shfl_xor_sync(0xffffffffu, s, o);
                if (lane == 0) sm[wid] = s;
                __syncthreads();
                float mu = 0.f;
#pragma unroll
                for (int i = 0; i < 8; i++) mu += sm[i];
                mu *= (1.0f / Cc);
                __syncthreads();
                float d0 = v0 - mu, d1 = v1 - mu;
                float s2 = d0 * d0 + d1 * d1;
#pragma unroll
                for (int o = 16; o > 0; o >>= 1) s2 += __shfl_xor_sync(0xffffffffu, s2, o);
                if (lane == 0) sm[wid] = s2;
                __syncthreads();
                float var = 0.f;
#pragma unroll
                for (int i = 0; i < 8; i++) var += sm[i];
                var *= (1.0f / Cc);
                float inv = rsqrtf(var + 1e-5f);
                size_t oo = ((size_t)t * Bc + b) * Cc;
                o_atts[oo + tid]       = d0 * inv * ln_g[tid]       + ln_b[tid];
                o_atts[oo + 256 + tid] = d1 * inv * ln_g[256 + tid] + ln_b[256 + tid];
            }
        }
        gsync();
    }
}

// -------------------------------- host ---------------------------------------
extern "C" void kernel_launch(void* const* d_in, const int* in_sizes, int n_in,
                              void* d_out, int out_size) {
    const float* y_emb   = (const float*)d_in[0];
    const float* context = (const float*)d_in[1];
    const float* h0      = (const float*)d_in[2];
    const float* c0      = (const float*)d_in[3];
    const float* xmask   = (const float*)d_in[4];
    const float* ymask   = (const float*)d_in[5];
    const float* cov0    = (const float*)d_in[6];
    const float* W_ih    = (const float*)d_in[7];
    const float* W_hh    = (const float*)d_in[8];
    const float* b_ih    = (const float*)d_in[9];
    const float* b_hh    = (const float*)d_in[10];
    const float* Wc_att  = (const float*)d_in[11];
    const float* b_att   = (const float*)d_in[12];
    const float* Wv_att  = (const float*)d_in[13];
    const float* bv_att  = (const float*)d_in[14];
    const float* W_comb  = (const float*)d_in[15];
    const float* U_att   = (const float*)d_in[16];
    const float* W_cov   = (const float*)d_in[17];
    const float* W_concat= (const float*)d_in[18];
    const float* ln_g    = (const float*)d_in[19];
    const float* ln_b    = (const float*)d_in[20];

    float* out    = (float*)d_out;
    float* o_hs   = out;
    float* o_cs   = o_hs + (size_t)TYc * Bc * Hc;
    float* o_ss   = o_cs + (size_t)TYc * Bc * Hc;
    float* o_atts = o_ss + (size_t)TYc * Bc * Hc;
    float* o_dists= o_atts + (size_t)TYc * Bc * Cc;
    float* o_Cs   = o_dists + (size_t)TYc * Bc * TXc;

    // precompute (5 small nodes)
    combine_bias<<<8, 256>>>(b_ih, b_hh);
    sgemm_nt_bias<<<dim3(Cc / 128, (TXc * Bc) / 128), 256>>>(context, Wc_att, b_att, Cc, 0);
    sgemm_nt_bias<<<dim3(Cc / 128, (TXc * Bc) / 128), 256>>>(context, Wv_att, bv_att, Cc, 1);
    sgemm_nt_bias<<<dim3(G4c / 128, (TYc * Bc) / 128), 256>>>(y_emb, W_ih, nullptr, G4c, 2);
    init_state<<<128, 256>>>(h0, c0, cov0);

    // entire 128-step recurrence in one persistent kernel (1 node)
    decoder_persistent<<<NBc, NTc>>>(xmask, ymask, W_hh, W_comb, U_att, W_cov,
                                     W_concat, ln_g, ln_b,
                                     o_hs, o_cs, o_ss, o_atts, o_dists, o_Cs);
}

// round 4
// speedup vs baseline: 1.0014x; 1.0014x over previous
#include <cuda_runtime.h>
#include <math.h>

// Problem constants
constexpr int TYc = 128;   // decode steps
constexpr int Bc  = 64;    // batch
constexpr int TXc = 400;   // encoder length
constexpr int Hc  = 512;
constexpr int Cc  = 512;
constexpr int NHc = 8;
constexpr int G4c = 4 * Hc;  // 2048
constexpr int NBc = 128;     // persistent blocks (<=148 SMs -> all resident)
constexpr int NTc = 256;     // threads per block

// ---------------- device scratch (static: no allocations allowed) ----------
__device__ float g_pctx[(size_t)TXc * Bc * Cc];   // [t][b][c] key projection
__device__ float g_pv  [(size_t)TXc * Bc * Cc];   // [t][b][c] value projection
__device__ float g_xw  [(size_t)TYc * Bc * G4c];  // [t][b][4H] x@W_ih.T + b_ih + b_hh
__device__ float g_bias4[G4c];
__device__ float g_h[2][Bc * Hc];
__device__ float g_c[2][Bc * Hc];
__device__ float g_hq [Bc * Cc];
__device__ float g_e  [Bc * NHc * TXc];   // scores [b][h][t]
__device__ float g_w  [Bc * NHc * TXc];   // softmax weights [b][h][t]
__device__ float g_acc[Bc * TXc];         // coverage accumulator
__device__ float g_ctx[Bc * Cc];          // attention context vector
__device__ float g_att[Bc * Cc];          // ctx @ W_concat.T (pre-LN)
__device__ unsigned g_bar_count;          // zero-initialized
__device__ unsigned g_bar_gen;

__device__ __forceinline__ float sigf(float x) { return 1.0f / (1.0f + __expf(-x)); }
__device__ __forceinline__ float tanh_acc(float x) {
    // tanh(x) = 1 - 2/(exp(2|x|)+1), abs err ~1e-7; exp overflow -> 1 (correct)
    float e = __expf(2.0f * fabsf(x));
    float r = 1.0f - 2.0f / (e + 1.0f);
    return copysignf(r, x);
}

// ---------------- grid-wide barrier (all NBc blocks resident) ---------------
__device__ __forceinline__ void gsync() {
    __threadfence();                 // order my writes; CCTL.IVALL on sm_103a
    __syncthreads();
    if (threadIdx.x == 0) {
        unsigned gen = *(volatile unsigned*)&g_bar_gen;
        if (atomicAdd(&g_bar_count, 1u) == NBc - 1) {
            g_bar_count = 0;
            __threadfence();
            atomicExch(&g_bar_gen, gen + 1);
        } else {
            while (*(volatile unsigned*)&g_bar_gen == gen) {}
        }
        __threadfence();             // invalidate L1 before reading others' data
    }
    __syncthreads();
}

// ---------------- precompute: C[m][n] = sum_k A[m][k]*B[n][k] + bias[n] -----
// K fixed at 512. tag selects output buffer (0=pctx,1=pv,2=xw with g_bias4).
__global__ void sgemm_nt_bias(const float* __restrict__ A, const float* __restrict__ Bm,
                              const float* __restrict__ bias, int N, int tag) {
    float* Cout = (tag == 0) ? g_pctx : (tag == 1) ? g_pv : g_xw;
    const float* bp = (tag == 2) ? g_bias4 : bias;
    const int K = 512;
    __shared__ float As[8][128];
    __shared__ float Bs[8][128];
    int bm = blockIdx.y * 128, bn = blockIdx.x * 128;
    int tid = threadIdx.x;
    int lr = tid >> 1, lc = (tid & 1) * 4;
    int ty = tid >> 4, tx = tid & 15;
    float acc[8][8] = {};
    const float* Ap = A + (size_t)(bm + lr) * K + lc;
    const float* Bp = Bm + (size_t)(bn + lr) * K + lc;
    for (int k0 = 0; k0 < K; k0 += 8) {
        float4 a4 = *(const float4*)(Ap + k0);
        float4 b4 = *(const float4*)(Bp + k0);
        As[lc][lr] = a4.x; As[lc + 1][lr] = a4.y; As[lc + 2][lr] = a4.z; As[lc + 3][lr] = a4.w;
        Bs[lc][lr] = b4.x; Bs[lc + 1][lr] = b4.y; Bs[lc + 2][lr] = b4.z; Bs[lc + 3][lr] = b4.w;
        __syncthreads();
#pragma unroll
        for (int kk = 0; kk < 8; kk++) {
            float ar[8], br[8];
            *(float4*)&ar[0] = *(const float4*)&As[kk][ty * 8];
            *(float4*)&ar[4] = *(const float4*)&As[kk][ty * 8 + 4];
            *(float4*)&br[0] = *(const float4*)&Bs[kk][tx * 8];
            *(float4*)&br[4] = *(const float4*)&Bs[kk][tx * 8 + 4];
#pragma unroll
            for (int i = 0; i < 8; i++)
#pragma unroll
                for (int j = 0; j < 8; j++) acc[i][j] = fmaf(ar[i], br[j], acc[i][j]);
        }
        __syncthreads();
    }
#pragma unroll
    for (int i = 0; i < 8; i++) {
        size_t m = bm + ty * 8 + i;
#pragma unroll
        for (int j = 0; j < 8; j += 4) {
            int n = bn + tx * 8 + j;
            float4 o;
            o.x = acc[i][j + 0] + bp[n + 0];
            o.y = acc[i][j + 1] + bp[n + 1];
            o.z = acc[i][j + 2] + bp[n + 2];
            o.w = acc[i][j + 3] + bp[n + 3];
            *(float4*)&Cout[m * N + n] = o;
        }
    }
}

__global__ void combine_bias(const float* __restrict__ bi, const float* __restrict__ bh) {
    int i = blockIdx.x * 256 + threadIdx.x;
    if (i < G4c) g_bias4[i] = bi[i] + bh[i];
}

__global__ void init_state(const float* __restrict__ h0, const float* __restrict__ c0,
                           const float* __restrict__ cov) {
    int i = blockIdx.x * 256 + threadIdx.x;
    if (i < Bc * Hc) { g_h[0][i] = h0[i]; g_c[0][i] = c0[i]; }
    if (i < Bc * TXc) g_acc[i] = cov[i];
}

// ---------------- the whole recurrent loop as ONE persistent kernel ---------
__global__ void __launch_bounds__(NTc, 1)
decoder_persistent(const float* __restrict__ xmask, const float* __restrict__ ymask,
                   const float* __restrict__ W_hh, const float* __restrict__ W_comb,
                   const float* __restrict__ U_att, const float* __restrict__ W_cov,
                   const float* __restrict__ W_concat, const float* __restrict__ ln_g,
                   const float* __restrict__ ln_b,
                   float* __restrict__ o_hs, float* __restrict__ o_cs,
                   float* __restrict__ o_ss, float* __restrict__ o_atts,
                   float* __restrict__ o_dists, float* __restrict__ o_Cs) {
    __shared__ float sm[8256];   // phase-overlaid scratch (max 33 KB)
    const int tid  = threadIdx.x;
    const int bk   = blockIdx.x;
    const int wid  = tid >> 5;
    const int lane = tid & 31;
    const int tx   = tid & 63;   // batch lane for GEMM phases
    const int ty   = tid >> 6;   // 0..3

    for (int t = 0; t < TYc; t++) {
        const int ph = t & 1;    // read g_h[ph]/g_c[ph], write [ph^1]

        // ===== Phase A: gates = h_prev @ W_hh.T (+xw), LSTM cell update =====
        {
            const int u0 = bk * 4;
            const float* hprev = g_h[ph];
            float* Wt = sm;            // [16][256]
            float* Ht = sm + 4096;     // [64][65]
            float a0 = 0.f, a1 = 0.f, a2 = 0.f, a3 = 0.f;
            for (int kh = 0; kh < 2; kh++) {
#pragma unroll
                for (int q = 0; q < 4; q++) {           // load W tile 16x256
                    int idx = q * 256 + tid;            // float4 index
                    int r = idx >> 6;
                    int k4 = (idx & 63) * 4;
                    int j = (r >> 2) * Hc + u0 + (r & 3);
                    float4 v = *(const float4*)&W_hh[(size_t)j * Hc + kh * 256 + k4];
                    float* w = &Wt[r * 256 + k4];
                    w[0] = v.x; w[1] = v.y; w[2] = v.z; w[3] = v.w;
                }
                for (int kt = 0; kt < 4; kt++) {
                    __syncthreads();
#pragma unroll
                    for (int q = 0; q < 4; q++) {       // load h tile 64x64
                        int idx = q * 256 + tid;
                        int b = idx >> 4;
                        int k4 = (idx & 15) * 4;
                        float4 v = *(const float4*)&hprev[b * Hc + kh * 256 + kt * 64 + k4];
                        float* hh = &Ht[b * 65 + k4];
                        hh[0] = v.x; hh[1] = v.y; hh[2] = v.z; hh[3] = v.w;
                    }
                    __syncthreads();
#pragma unroll
                    for (int kk = 0; kk < 64; kk++) {
                        float hv = Ht[tx * 65 + kk];
                        int kw = kt * 64 + kk;
                        a0 = fmaf(Wt[(0 * 4 + ty) * 256 + kw], hv, a0);
                        a1 = fmaf(Wt[(1 * 4 + ty) * 256 + kw], hv, a1);
                        a2 = fmaf(Wt[(2 * 4 + ty) * 256 + kw], hv, a2);
                        a3 = fmaf(Wt[(3 * 4 + ty) * 256 + kw], hv, a3);
                    }
                }
                __syncthreads();   // before W tile reload
            }
            // cell update: one (b=tx, u=u0+ty) per thread
            const int u = u0 + ty;
            const float* xw = &g_xw[((size_t)t * Bc + tx) * G4c];
            float gi = a0 + xw[u];
            float gf = a1 + xw[Hc + u];
            float gg = a2 + xw[2 * Hc + u];
            float go = a3 + xw[3 * Hc + u];
            float co = g_c[ph][tx * Hc + u];
            float ho = hprev[tx * Hc + u];
            float c1 = sigf(gf) * co + sigf(gi) * tanh_acc(gg);
            float h1 = sigf(go) * tanh_acc(c1);
            float m = ymask[t * Bc + tx];
            h1 = m * h1 + (1.0f - m) * ho;
            c1 = m * c1 + (1.0f - m) * co;
            g_h[ph ^ 1][tx * Hc + u] = h1;
            g_c[ph ^ 1][tx * Hc + u] = c1;
            size_t oo = ((size_t)t * Bc + tx) * Hc + u;
            o_hs[oo] = h1; o_ss[oo] = h1; o_cs[oo] = c1;
        }
        gsync();

        // ===== Phase B: hq = [h1,c1] @ W_comb.T (K=1024) =====
        {
            const int c0 = bk * 4;
            float* Wt = sm;            // [4][1024]
            float* St = sm + 4096;     // [64][65]
#pragma unroll
            for (int q = 0; q < 4; q++) {
                int idx = q * 256 + tid;
                int r = idx >> 8;
                int k4 = (idx & 255) * 4;
                float4 v = *(const float4*)&W_comb[(size_t)(c0 + r) * 1024 + k4];
                float* w = &Wt[r * 1024 + k4];
                w[0] = v.x; w[1] = v.y; w[2] = v.z; w[3] = v.w;
            }
            float acc = 0.f;
            for (int kt = 0; kt < 16; kt++) {
                const float* src = (kt < 8) ? g_h[ph ^ 1] : g_c[ph ^ 1];
                int koff = (kt & 7) * 64;
                __syncthreads();
#pragma unroll
                for (int q = 0; q < 4; q++) {
                    int idx = q * 256 + tid;
                    int b = idx >> 4;
                    int k4 = (idx & 15) * 4;
                    float4 v = *(const float4*)&src[b * Hc + koff + k4];
                    float* s = &St[b * 65 + k4];
                    s[0] = v.x; s[1] = v.y; s[2] = v.z; s[3] = v.w;
                }
                __syncthreads();
#pragma unroll
                for (int kk = 0; kk < 64; kk++)
                    acc = fmaf(Wt[ty * 1024 + kt * 64 + kk], St[tx * 65 + kk], acc);
            }
            g_hq[tx * Cc + c0 + ty] = acc;
        }
        gsync();

        // ===== Phase C: e[b][h][t'] = sum_d tanh(pctx+hq+cov)*xm*U =====
        {
            for (int i = tid; i < 1024; i += NTc)
                sm[i] = (i < 512) ? U_att[i] : W_cov[i - 512];
            __syncthreads();
            const int wg = bk * 8 + wid;     // 0..1023, 16 warps per b
            const int cb = wg >> 4;          // batch
            const int t0 = wg & 15;
            float hqr[16];
#pragma unroll
            for (int i = 0; i < 16; i++) hqr[i] = g_hq[cb * Cc + i * 32 + lane];
            for (int i = 0; i < 25; i++) {
                int ts = t0 + 16 * i;        // encoder position
                const float* pc = &g_pctx[((size_t)ts * Bc + cb) * Cc];
                float cov = g_acc[cb * TXc + ts];
                float xm = xmask[ts * Bc + cb];
#pragma unroll
                for (int hh = 0; hh < 8; hh++) {
                    float s = 0.f;
#pragma unroll
                    for (int ii = 0; ii < 2; ii++) {
                        int c = hh * 64 + ii * 32 + lane;
                        float arg = pc[c] + hqr[hh * 2 + ii] + cov * sm[512 + c];
                        s = fmaf(tanh_acc(arg) * xm, sm[c], s);
                    }
#pragma unroll
                    for (int o = 16; o > 0; o >>= 1) s += __shfl_xor_sync(0xffffffffu, s, o);
                    if (lane == 0) g_e[(cb * NHc + hh) * TXc + ts] = s;
                }
            }
        }
        gsync();

        // ===== Phase D: softmax over t' per (b,h); coverage/dists outputs ===
        {
            const int wg = bk * 8 + wid;
            if (wg < Bc * NHc) {
                const int b = wg >> 3, hh = wg & 7;
                const float* ep = &g_e[wg * TXc];
                float ev[13];
                float mx = -3.4e38f;
#pragma unroll
                for (int i = 0; i < 13; i++) {
                    int ts = lane + i * 32;
                    float v = (ts < TXc) ? ep[ts] : -3.4e38f;
                    ev[i] = v; mx = fmaxf(mx, v);
                }
#pragma unroll
                for (int o = 16; o > 0; o >>= 1) mx = fmaxf(mx, __shfl_xor_sync(0xffffffffu, mx, o));
                float sum = 0.f;
#pragma unroll
                for (int i = 0; i < 13; i++) {
                    int ts = lane + i * 32;
                    if (ts < TXc) {
                        float v = __expf(ev[i] - mx) * xmask[ts * Bc + b];
                        ev[i] = v; sum += v;
                    }
                }
#pragma unroll
                for (int o = 16; o > 0; o >>= 1) sum += __shfl_xor_sync(0xffffffffu, sum, o);
                float inv = 1.0f / (sum + 1e-6f);
                float* wp = &g_w[wg * TXc];
#pragma unroll
                for (int i = 0; i < 13; i++) {
                    int ts = lane + i * 32;
                    if (ts < TXc) {
                        float w = ev[i] * inv;
                        wp[ts] = w;
                        if (hh == 0) {
                            float a = g_acc[b * TXc + ts];
                            o_Cs[((size_t)t * Bc + b) * TXc + ts] = a;
                            o_dists[((size_t)t * Bc + b) * TXc + ts] = w;
                            g_acc[b * TXc + ts] = a + w;
                        }
                    }
                }
            }
        }
        gsync();

        // ===== Phase E: ctx[b][c] = sum_t' w[b][h(c)][t'] * pv[t'][b][c] ====
        {
            const int b = bk >> 1, half = bk & 1;
            for (int idx = tid; idx < 4 * TXc; idx += NTc) {
                int hh = idx / TXc, ts = idx - hh * TXc;
                sm[idx] = g_w[(b * NHc + half * 4 + hh) * TXc + ts];
            }
            __syncthreads();
            const int c = half * 256 + tid;
            const float* wsp = &sm[(tid >> 6) * TXc];
            const float* pvp = &g_pv[(size_t)b * Cc + c];
            float a0 = 0.f, a1 = 0.f, a2 = 0.f, a3 = 0.f;
#pragma unroll 2
            for (int ts = 0; ts < TXc; ts += 4) {
                a0 = fmaf(pvp[(size_t)(ts + 0) * Bc * Cc], wsp[ts + 0], a0);
                a1 = fmaf(pvp[(size_t)(ts + 1) * Bc * Cc], wsp[ts + 1], a1);
                a2 = fmaf(pvp[(size_t)(ts + 2) * Bc * Cc], wsp[ts + 2], a2);
                a3 = fmaf(pvp[(size_t)(ts + 3) * Bc * Cc], wsp[ts + 3], a3);
            }
            g_ctx[b * Cc + c] = (a0 + a1) + (a2 + a3);
        }
        gsync();

        // ===== Phase F1: att = ctx @ W_concat.T (K=512) =====
        {
            const int c0 = bk * 4;
            float* Wt = sm;            // [4][512]
            float* St = sm + 2048;     // [64][65]
#pragma unroll
            for (int q = 0; q < 2; q++) {
                int idx = q * 256 + tid;
                int r = idx >> 7;
                int k4 = (idx & 127) * 4;
                float4 v = *(const float4*)&W_concat[(size_t)(c0 + r) * Cc + k4];
                float* w = &Wt[r * 512 + k4];
                w[0] = v.x; w[1] = v.y; w[2] = v.z; w[3] = v.w;
            }
            float acc = 0.f;
            for (int kt = 0; kt < 8; kt++) {
                __syncthreads();
#pragma unroll
                for (int q = 0; q < 4; q++) {
                    int idx = q * 256 + tid;
                    int b = idx >> 4;
                    int k4 = (idx & 15) * 4;
                    float4 v = *(const float4*)&g_ctx[b * Cc + kt * 64 + k4];
                    float* s = &St[b * 65 + k4];
                    s[0] = v.x; s[1] = v.y; s[2] = v.z; s[3] = v.w;
                }
                __syncthreads();
#pragma unroll
                for (int kk = 0; kk < 64; kk++)
                    acc = fmaf(Wt[ty * 512 + kt * 64 + kk], St[tx * 65 + kk], acc);
            }
            g_att[tx * Cc + c0 + ty] = acc;
        }
        gsync();

        // ===== Phase F2: LayerNorm -> o_atts =====
        {
            if (bk < Bc) {
                const int b = bk;
                float v0 = g_att[b * Cc + tid];
                float v1 = g_att[b * Cc + 256 + tid];
                float s = v0 + v1;
#pragma unroll
                for (int o = 16; o > 0; o >>= 1) s += __shfl_xor_sync(0xffffffffu, s, o);
                if (lane == 0) sm[wid] = s;
                __syncthreads();
                float mu = 0.f;
#pragma unroll
                for (int i = 0; i < 8; i++) mu += sm[i];
                mu *= (1.0f / Cc);
                __syncthreads();
                float d0 = v0 - mu, d1 = v1 - mu;
                float s2 = d0 * d0 + d1 * d1;
#pragma unroll
                for (int o = 16; o > 0; o >>= 1) s2 += __shfl_xor_sync(0xffffffffu, s2, o);
                if (lane == 0) sm[wid] = s2;
                __syncthreads();
                float var = 0.f;
#pragma unroll
                for (int i = 0; i < 8; i++) var += sm[i];
                var *= (1.0f / Cc);
                float inv = rsqrtf(var + 1e-5f);
                size_t oo = ((size_t)t * Bc + b) * Cc;
                o_atts[oo + tid]       = d0 * inv * ln_g[tid]       + ln_b[tid];
                o_atts[oo + 256 + tid] = d1 * inv * ln_g[256 + tid] + ln_b[256 + tid];
            }
        }
        gsync();
    }
}

// -------------------------------- host ---------------------------------------
extern "C" void kernel_launch(void* const* d_in, const int* in_sizes, int n_in,
                              void* d_out, int out_size) {
    const float* y_emb   = (const float*)d_in[0];
    const float* context = (const float*)d_in[1];
    const float* h0      = (const float*)d_in[2];
    const float* c0      = (const float*)d_in[3];
    const float* xmask   = (const float*)d_in[4];
    const float* ymask   = (const float*)d_in[5];
    const float* cov0    = (const float*)d_in[6];
    const float* W_ih    = (const float*)d_in[7];
    const float* W_hh    = (const float*)d_in[8];
    const float* b_ih    = (const float*)d_in[9];
    const float* b_hh    = (const float*)d_in[10];
    const float* Wc_att  = (const float*)d_in[11];
    const float* b_att   = (const float*)d_in[12];
    const float* Wv_att  = (const float*)d_in[13];
    const float* bv_att  = (const float*)d_in[14];
    const float* W_comb  = (const float*)d_in[15];
    const float* U_att   = (const float*)d_in[16];
    const float* W_cov   = (const float*)d_in[17];
    const float* W_concat= (const float*)d_in[18];
    const float* ln_g    = (const float*)d_in[19];
    const float* ln_b    = (const float*)d_in[20];

    float* out    = (float*)d_out;
    float* o_hs   = out;
    float* o_cs   = o_hs + (size_t)TYc * Bc * Hc;
    float* o_ss   = o_cs + (size_t)TYc * Bc * Hc;
    float* o_atts = o_ss + (size_t)TYc * Bc * Hc;
    float* o_dists= o_atts + (size_t)TYc * Bc * Cc;
    float* o_Cs   = o_dists + (size_t)TYc * Bc * TXc;

    // precompute (5 small nodes)
    combine_bias<<<8, 256>>>(b_ih, b_hh);
    sgemm_nt_bias<<<dim3(Cc / 128, (TXc * Bc) / 128), 256>>>(context, Wc_att, b_att, Cc, 0);
    sgemm_nt_bias<<<dim3(Cc / 128, (TXc * Bc) / 128), 256>>>(context, Wv_att, bv_att, Cc, 1);
    sgemm_nt_bias<<<dim3(G4c / 128, (TYc * Bc) / 128), 256>>>(y_emb, W_ih, nullptr, G4c, 2);
    init_state<<<128, 256>>>(h0, c0, cov0);

    // entire 128-step recurrence in one persistent kernel (1 node)
    decoder_persistent<<<NBc, NTc>>>(xmask, ymask, W_hh, W_comb, U_att, W_cov,
                                     W_concat, ln_g, ln_b,
                                     o_hs, o_cs, o_ss, o_atts, o_dists, o_Cs);
}

// round 5
// speedup vs baseline: 4.2926x; 4.2868x over previous
#include <cuda_runtime.h>
#include <math.h>

constexpr int TYc=128, Bc=64, TXc=400, Hc=512, Cc=512, G4c=2048;
constexpr int NBc=128, NTc=1024;

// device scratch
__device__ float g_pctx[(size_t)TXc*Bc*Cc];
__device__ float g_pv  [(size_t)TXc*Bc*Cc];
__device__ float g_xw  [(size_t)TYc*Bc*G4c];
__device__ float g_bias4[G4c];
__device__ float g_sT[2][1024*Bc];   // [k][b]; rows 0-511=h, 512-1023=c
__device__ float g_hq [Bc*Cc];
__device__ float g_e  [Bc*8*TXc];
__device__ float g_w  [Bc*8*TXc];
__device__ float g_acc[Bc*TXc];
__device__ float g_ctxT[Cc*Bc];      // [c][b]
__device__ float g_att[Bc*Cc];
__device__ unsigned g_bar_count, g_bar_gen;

// smem layout (floats)
constexpr int OFF_WHH=0;            // 16x520
constexpr int OFF_WCB=8320;         // 4x1040
constexpr int OFF_WCT=12480;        // 4x520
constexpr int OFF_U  =14560;
constexpr int OFF_WC =15072;
constexpr int OFF_LNG=15584;
constexpr int OFF_LNB=16096;
constexpr int OFF_RED=16608;        // 16384
constexpr int OFF_GATE=32992;       // 1024
constexpr int OFF_SW4=34016;        // 4x408
constexpr int SMEM_FLOATS=35648;

__device__ __forceinline__ float sigf(float x){ return 1.0f/(1.0f+__expf(-x)); }
__device__ __forceinline__ float tanh_acc(float x){
    float e=__expf(2.0f*fabsf(x));
    float r=1.0f-2.0f/(e+1.0f);
    return copysignf(r,x);
}
__device__ __forceinline__ float tanh_fast(float x){
    float r; asm("tanh.approx.f32 %0,%1;":"=f"(r):"f"(x)); return r;
}

__device__ __forceinline__ void gsync(){
    __syncthreads();
    if(threadIdx.x==0){
        __threadfence();
        unsigned gen=*(volatile unsigned*)&g_bar_gen;
        if(atomicAdd(&g_bar_count,1u)==NBc-1){
            g_bar_count=0; __threadfence(); atomicExch(&g_bar_gen,gen+1);
        } else {
            while(*(volatile unsigned*)&g_bar_gen==gen){}
        }
        __threadfence();
    }
    __syncthreads();
}

// precompute GEMM: C[m][n]=sum_k A[m][k]*B[n][k]+bias[n], K=512
__global__ void sgemm_nt_bias(const float* __restrict__ A,const float* __restrict__ Bm,
                              const float* __restrict__ bias,int N,int tag){
    float* Cout=(tag==0)?g_pctx:(tag==1)?g_pv:g_xw;
    const float* bp=(tag==2)?g_bias4:bias;
    const int K=512;
    __shared__ float As[8][128], Bs[8][128];
    int bm=blockIdx.y*128, bn=blockIdx.x*128;
    int tid=threadIdx.x;
    int lr=tid>>1, lc=(tid&1)*4;
    int ty=tid>>4, tx=tid&15;
    float acc[8][8]={};
    const float* Ap=A+(size_t)(bm+lr)*K+lc;
    const float* Bp=Bm+(size_t)(bn+lr)*K+lc;
    for(int k0=0;k0<K;k0+=8){
        float4 a4=*(const float4*)(Ap+k0);
        float4 b4=*(const float4*)(Bp+k0);
        As[lc][lr]=a4.x; As[lc+1][lr]=a4.y; As[lc+2][lr]=a4.z; As[lc+3][lr]=a4.w;
        Bs[lc][lr]=b4.x; Bs[lc+1][lr]=b4.y; Bs[lc+2][lr]=b4.z; Bs[lc+3][lr]=b4.w;
        __syncthreads();
#pragma unroll
        for(int kk=0;kk<8;kk++){
            float ar[8],br[8];
            *(float4*)&ar[0]=*(const float4*)&As[kk][ty*8];
            *(float4*)&ar[4]=*(const float4*)&As[kk][ty*8+4];
            *(float4*)&br[0]=*(const float4*)&Bs[kk][tx*8];
            *(float4*)&br[4]=*(const float4*)&Bs[kk][tx*8+4];
#pragma unroll
            for(int i=0;i<8;i++)
#pragma unroll
                for(int j=0;j<8;j++) acc[i][j]=fmaf(ar[i],br[j],acc[i][j]);
        }
        __syncthreads();
    }
#pragma unroll
    for(int i=0;i<8;i++){
        size_t m=bm+ty*8+i;
#pragma unroll
        for(int j=0;j<8;j+=4){
            int n=bn+tx*8+j;
            float4 o;
            o.x=acc[i][j+0]+bp[n+0]; o.y=acc[i][j+1]+bp[n+1];
            o.z=acc[i][j+2]+bp[n+2]; o.w=acc[i][j+3]+bp[n+3];
            *(float4*)&Cout[m*N+n]=o;
        }
    }
}

__global__ void combine_bias(const float* __restrict__ bi,const float* __restrict__ bh){
    int i=blockIdx.x*256+threadIdx.x;
    if(i<G4c) g_bias4[i]=bi[i]+bh[i];
}

__global__ void init_state(const float* __restrict__ h0,const float* __restrict__ c0,
                           const float* __restrict__ cov){
    int i=blockIdx.x*256+threadIdx.x;
    if(i<Bc*Hc){ int b=i>>9,u=i&511; g_sT[0][u*64+b]=h0[i]; g_sT[0][(512+u)*64+b]=c0[i]; }
    if(i<Bc*TXc) g_acc[i]=cov[i];
}

__global__ void __launch_bounds__(NTc,1)
decoder_persistent(const float* __restrict__ xmask,const float* __restrict__ ymask,
                   const float* __restrict__ W_hh,const float* __restrict__ W_comb,
                   const float* __restrict__ U_att,const float* __restrict__ W_cov,
                   const float* __restrict__ W_concat,const float* __restrict__ ln_g,
                   const float* __restrict__ ln_b,
                   float* __restrict__ o_hs,float* __restrict__ o_cs,
                   float* __restrict__ o_ss,float* __restrict__ o_atts,
                   float* __restrict__ o_dists,float* __restrict__ o_Cs){
    extern __shared__ float sm[];
    const int tid=threadIdx.x, bk=blockIdx.x;
    const int wid=tid>>5, lane=tid&31;

    // ---- one-time weight preload ----
    for(int f=tid;f<8192;f+=NTc){ int jj=f>>9,k=f&511;
        sm[OFF_WHH+jj*520+k]=W_hh[(size_t)((jj>>2)*512+bk*4+(jj&3))*512+k]; }
    for(int f=tid;f<4096;f+=NTc){ int c=f>>10,k=f&1023;
        sm[OFF_WCB+c*1040+k]=W_comb[(size_t)(bk*4+c)*1024+k]; }
    for(int f=tid;f<2048;f+=NTc){ int c=f>>9,k=f&511;
        sm[OFF_WCT+c*520+k]=W_concat[(size_t)(bk*4+c)*512+k]; }
    for(int f=tid;f<512;f+=NTc){
        sm[OFF_U+f]=U_att[f]; sm[OFF_WC+f]=W_cov[f];
        sm[OFF_LNG+f]=ln_g[f]; sm[OFF_LNB+f]=ln_b[f]; }
    __syncthreads();

    for(int t=0;t<TYc;t++){
        const int ph=t&1;

        // ===== A: gates = h @ W_hh.T, then LSTM cell =====
        {
            const int ks=tid>>6, jg=(tid>>4)&3, bg=tid&15;
            const float* hT=g_sT[ph];
            float acc[4][4]={};
#pragma unroll 4
            for(int kk=0;kk<32;kk++){
                int k=ks*32+kk;
                float4 hv=*(const float4*)&hT[k*64+bg*4];
#pragma unroll
                for(int ji=0;ji<4;ji++){
                    float w=sm[OFF_WHH+(jg*4+ji)*520+k];
                    acc[ji][0]=fmaf(w,hv.x,acc[ji][0]);
                    acc[ji][1]=fmaf(w,hv.y,acc[ji][1]);
                    acc[ji][2]=fmaf(w,hv.z,acc[ji][2]);
                    acc[ji][3]=fmaf(w,hv.w,acc[ji][3]);
                }
            }
#pragma unroll
            for(int ji=0;ji<4;ji++)
#pragma unroll
                for(int bi=0;bi<4;bi++)
                    sm[OFF_RED+ks*1024+(jg*4+ji)*64+bg*4+bi]=acc[ji][bi];
            __syncthreads();
            {
                float s=0.f;
#pragma unroll
                for(int k2=0;k2<16;k2++) s+=sm[OFF_RED+k2*1024+tid];
                sm[OFF_GATE+tid]=s;
            }
            __syncthreads();
            if(tid<256){
                int ui=tid>>6, b=tid&63;
                int u=bk*4+ui;
                const float* xw=&g_xw[((size_t)t*64+b)*2048];
                float gi=sm[OFF_GATE+(0*4+ui)*64+b]+xw[u];
                float gf=sm[OFF_GATE+(1*4+ui)*64+b]+xw[512+u];
                float gg=sm[OFF_GATE+(2*4+ui)*64+b]+xw[1024+u];
                float go=sm[OFF_GATE+(3*4+ui)*64+b]+xw[1536+u];
                float ho=g_sT[ph][u*64+b];
                float co=g_sT[ph][(512+u)*64+b];
                float c1=sigf(gf)*co+sigf(gi)*tanh_acc(gg);
                float h1=sigf(go)*tanh_acc(c1);
                float m=ymask[t*64+b];
                h1=m*h1+(1.0f-m)*ho;
                c1=m*c1+(1.0f-m)*co;
                g_sT[ph^1][u*64+b]=h1;
                g_sT[ph^1][(512+u)*64+b]=c1;
                size_t oo=((size_t)t*64+b)*512+u;
                o_hs[oo]=h1; o_ss[oo]=h1; o_cs[oo]=c1;
            }
        }
        gsync();

        // ===== B: hq = [h,c] @ W_comb.T (K=1024) =====
        {
            const int ks=tid>>6, cl=(tid>>4)&3, bg=tid&15;
            const float* sT=g_sT[ph^1];
            float acc[4]={};
#pragma unroll 4
            for(int kk=0;kk<64;kk++){
                int k=ks*64+kk;
                float4 v=*(const float4*)&sT[k*64+bg*4];
                float w=sm[OFF_WCB+cl*1040+k];
                acc[0]=fmaf(w,v.x,acc[0]); acc[1]=fmaf(w,v.y,acc[1]);
                acc[2]=fmaf(w,v.z,acc[2]); acc[3]=fmaf(w,v.w,acc[3]);
            }
#pragma unroll
            for(int bi=0;bi<4;bi++) sm[OFF_RED+ks*256+cl*64+bg*4+bi]=acc[bi];
            __syncthreads();
            if(tid<256){
                int cl2=tid>>6, b=tid&63;
                float s=0.f;
#pragma unroll
                for(int k2=0;k2<16;k2++) s+=sm[OFF_RED+k2*256+tid];
                g_hq[b*512+bk*4+cl2]=s;
            }
        }
        gsync();

        // ===== C: scores e[b][h][ts] =====
        {
            const int b=bk>>1, tb=(bk&1)*200;
            float hqr[16];
#pragma unroll
            for(int ii=0;ii<16;ii++) hqr[ii]=g_hq[b*512+ii*32+lane];
            for(int i=0;i<7;i++){
                int tsl=wid+32*i;
                if(tsl<200){
                    int ts=tb+tsl;
                    float cov=g_acc[b*400+ts];
                    float xm=xmask[ts*64+b];
                    const float* pc=&g_pctx[((size_t)ts*64+b)*512];
                    float a[8]={};
#pragma unroll
                    for(int ii=0;ii<16;ii++){
                        int c=ii*32+lane;
                        float arg=pc[c]+hqr[ii]+cov*sm[OFF_WC+c];
                        a[ii>>1]=fmaf(tanh_fast(arg)*xm,sm[OFF_U+c],a[ii>>1]);
                    }
#pragma unroll
                    for(int hh=0;hh<8;hh++){
                        float s=a[hh];
#pragma unroll
                        for(int o=16;o>0;o>>=1) s+=__shfl_xor_sync(0xffffffffu,s,o);
                        if(lane==0) g_e[(b*8+hh)*400+ts]=s;
                    }
                }
            }
        }
        gsync();

        // ===== D: softmax over ts per (b,h) =====
        {
            int gw=bk*32+wid;
            if(gw<512){
                int b=gw>>3, hh=gw&7;
                const float* ep=&g_e[gw*400];
                float ev[13]; float mx=-3.4e38f;
#pragma unroll
                for(int i=0;i<13;i++){ int ts=lane+32*i;
                    float v=(ts<400)?ep[ts]:-3.4e38f; ev[i]=v; mx=fmaxf(mx,v); }
#pragma unroll
                for(int o=16;o>0;o>>=1) mx=fmaxf(mx,__shfl_xor_sync(0xffffffffu,mx,o));
                float sum=0.f;
#pragma unroll
                for(int i=0;i<13;i++){ int ts=lane+32*i;
                    if(ts<400){ float v=__expf(ev[i]-mx)*xmask[ts*64+b]; ev[i]=v; sum+=v; } }
#pragma unroll
                for(int o=16;o>0;o>>=1) sum+=__shfl_xor_sync(0xffffffffu,sum,o);
                float inv=1.0f/(sum+1e-6f);
                float* wp=&g_w[gw*400];
#pragma unroll
                for(int i=0;i<13;i++){ int ts=lane+32*i;
                    if(ts<400){
                        float w=ev[i]*inv; wp[ts]=w;
                        if(hh==0){
                            float a=g_acc[b*400+ts];
                            o_Cs[((size_t)t*64+b)*400+ts]=a;
                            o_dists[((size_t)t*64+b)*400+ts]=w;
                            g_acc[b*400+ts]=a+w;
                        }
                    } }
            }
        }
        gsync();

        // ===== E: ctx[c][b] = sum_ts w[b][h(c)][ts]*pv[ts][b][c] =====
        {
            const int b=bk>>1, ch=bk&1;
            for(int q=0;q<2;q++){
                int f=q*1024+tid;
                if(f<1600){ int hl=f/400, ts=f-hl*400;
                    sm[OFF_SW4+hl*408+ts]=g_w[((size_t)(b*8+ch*4+hl))*400+ts]; }
            }
            __syncthreads();
            const int tq=tid>>6, cg=tid&63, hl=cg>>4;
            const int c=ch*256+cg*4;
            const float* pvp=&g_pv[(size_t)b*512+c];
            float4 acc=make_float4(0.f,0.f,0.f,0.f);
            int t0=tq*25;
#pragma unroll 5
            for(int tt=0;tt<25;tt++){
                int ts=t0+tt;
                float4 v=*(const float4*)&pvp[(size_t)ts*32768];
                float wv=sm[OFF_SW4+hl*408+ts];
                acc.x=fmaf(v.x,wv,acc.x); acc.y=fmaf(v.y,wv,acc.y);
                acc.z=fmaf(v.z,wv,acc.z); acc.w=fmaf(v.w,wv,acc.w);
            }
            *(float4*)&sm[OFF_RED+tq*256+cg*4]=acc;
            __syncthreads();
            if(tid<256){
                float s=0.f;
#pragma unroll
                for(int k2=0;k2<16;k2++) s+=sm[OFF_RED+k2*256+tid];
                g_ctxT[(ch*256+tid)*64+b]=s;
            }
        }
        gsync();

        // ===== F1: att = ctx @ W_concat.T (K=512) =====
        {
            const int ks=tid>>6, cl=(tid>>4)&3, bg=tid&15;
            float acc[4]={};
#pragma unroll 4
            for(int kk=0;kk<32;kk++){
                int k=ks*32+kk;
                float4 v=*(const float4*)&g_ctxT[k*64+bg*4];
                float w=sm[OFF_WCT+cl*520+k];
                acc[0]=fmaf(w,v.x,acc[0]); acc[1]=fmaf(w,v.y,acc[1]);
                acc[2]=fmaf(w,v.z,acc[2]); acc[3]=fmaf(w,v.w,acc[3]);
            }
#pragma unroll
            for(int bi=0;bi<4;bi++) sm[OFF_RED+ks*256+cl*64+bg*4+bi]=acc[bi];
            __syncthreads();
            if(tid<256){
                int cl2=tid>>6, b=tid&63;
                float s=0.f;
#pragma unroll
                for(int k2=0;k2<16;k2++) s+=sm[OFF_RED+k2*256+tid];
                g_att[b*512+bk*4+cl2]=s;
            }
        }
        gsync();

        // ===== F2: LayerNorm -> o_atts (blocks 0..63) =====
        if(bk<64){
            float v=0.f;
            if(tid<512) v=g_att[bk*512+tid];
            float s=v;
#pragma unroll
            for(int o=16;o>0;o>>=1) s+=__shfl_xor_sync(0xffffffffu,s,o);
            if(lane==0) sm[OFF_RED+wid]=s;
            __syncthreads();
            float mu=0.f;
#pragma unroll
            for(int i=0;i<16;i++) mu+=sm[OFF_RED+i];
            mu*=(1.0f/512.0f);
            float d=v-mu;
            float s2=(tid<512)?d*d:0.f;
#pragma unroll
            for(int o=16;o>0;o>>=1) s2+=__shfl_xor_sync(0xffffffffu,s2,o);
            if(lane==0) sm[OFF_RED+16+wid]=s2;
            __syncthreads();
            float var=0.f;
#pragma unroll
            for(int i=0;i<16;i++) var+=sm[OFF_RED+16+i];
            var*=(1.0f/512.0f);
            __syncthreads();   // protect sRED before next A overwrites
            if(tid<512){
                float inv=rsqrtf(var+1e-5f);
                o_atts[((size_t)t*64+bk)*512+tid]=d*inv*sm[OFF_LNG+tid]+sm[OFF_LNB+tid];
            }
        }
    }
}

extern "C" void kernel_launch(void* const* d_in,const int* in_sizes,int n_in,
                              void* d_out,int out_size){
    const float* y_emb   =(const float*)d_in[0];
    const float* context =(const float*)d_in[1];
    const float* h0      =(const float*)d_in[2];
    const float* c0      =(const float*)d_in[3];
    const float* xmask   =(const float*)d_in[4];
    const float* ymask   =(const float*)d_in[5];
    const float* cov0    =(const float*)d_in[6];
    const float* W_ih    =(const float*)d_in[7];
    const float* W_hh    =(const float*)d_in[8];
    const float* b_ih    =(const float*)d_in[9];
    const float* b_hh    =(const float*)d_in[10];
    const float* Wc_att  =(const float*)d_in[11];
    const float* b_att   =(const float*)d_in[12];
    const float* Wv_att  =(const float*)d_in[13];
    const float* bv_att  =(const float*)d_in[14];
    const float* W_comb  =(const float*)d_in[15];
    const float* U_att   =(const float*)d_in[16];
    const float* W_cov   =(const float*)d_in[17];
    const float* W_concat=(const float*)d_in[18];
    const float* ln_g    =(const float*)d_in[19];
    const float* ln_b    =(const float*)d_in[20];

    float* out    =(float*)d_out;
    float* o_hs   =out;
    float* o_cs   =o_hs+(size_t)TYc*Bc*Hc;
    float* o_ss   =o_cs+(size_t)TYc*Bc*Hc;
    float* o_atts =o_ss+(size_t)TYc*Bc*Hc;
    float* o_dists=o_atts+(size_t)TYc*Bc*Cc;
    float* o_Cs   =o_dists+(size_t)TYc*Bc*TXc;

    combine_bias<<<8,256>>>(b_ih,b_hh);
    sgemm_nt_bias<<<dim3(Cc/128,(TXc*Bc)/128),256>>>(context,Wc_att,b_att,Cc,0);
    sgemm_nt_bias<<<dim3(Cc/128,(TXc*Bc)/128),256>>>(context,Wv_att,bv_att,Cc,1);
    sgemm_nt_bias<<<dim3(G4c/128,(TYc*Bc)/128),256>>>(y_emb,W_ih,nullptr,G4c,2);
    init_state<<<128,256>>>(h0,c0,cov0);

    cudaFuncSetAttribute(decoder_persistent,
        cudaFuncAttributeMaxDynamicSharedMemorySize, SMEM_FLOATS*4);
    decoder_persistent<<<NBc,NTc,SMEM_FLOATS*4>>>(xmask,ymask,W_hh,W_comb,U_att,W_cov,
        W_concat,ln_g,ln_b,o_hs,o_cs,o_ss,o_atts,o_dists,o_Cs);
}